// round 5
// baseline (speedup 1.0000x reference)
#include <cuda_runtime.h>
#include <math.h>

#define L_TOTAL 32768
#define DMODEL  1024
#define NCHUNK  512
#define L_PER   (L_TOTAL / NCHUNK)   // 64
#define THREADS1 256

// Scratch (allocation-free rule: __device__ globals)
__device__ float g_partials[NCHUNK * DMODEL];   // 2 MB
__device__ float g_signal[DMODEL];

// Kernel 1: partial sums of sin over a 64-position chunk of L, all 1024 d.
__global__ void __launch_bounds__(THREADS1)
sin_partial_kernel(const float* __restrict__ x) {
    __shared__ float sa[L_PER];
    __shared__ float sc[L_PER];
    const int chunk = blockIdx.x;
    const int l0 = chunk * L_PER;
    const int tid = threadIdx.x;

    if (tid < L_PER) {
        float xv = x[l0 + tid];
        float a  = 6.28318530717958647692f * xv;          // 2*pi*x[l]
        float p  = logf(1.0f + (float)(l0 + tid));        // log1p(l), exact arg
        sa[tid] = a;
        sc[tid] = a * p;                                  // phase offset
    }
    __syncthreads();

    const float inv = 1.0f / (float)(DMODEL - 1);
    const float t0 = (float)(tid        ) * inv;
    const float t1 = (float)(tid +  256 ) * inv;
    const float t2 = (float)(tid +  512 ) * inv;
    const float t3 = (float)(tid +  768 ) * inv;

    float acc0 = 0.f, acc1 = 0.f, acc2 = 0.f, acc3 = 0.f;

    #pragma unroll 8
    for (int l = 0; l < L_PER; ++l) {
        const float a = sa[l];
        const float c = sc[l];
        acc0 += __sinf(fmaf(a, t0, c));
        acc1 += __sinf(fmaf(a, t1, c));
        acc2 += __sinf(fmaf(a, t2, c));
        acc3 += __sinf(fmaf(a, t3, c));
    }

    float* out = g_partials + chunk * DMODEL;
    out[tid        ] = acc0;
    out[tid +  256 ] = acc1;
    out[tid +  512 ] = acc2;
    out[tid +  768 ] = acc3;
}

// Kernel 2: deterministic fixed-order reduction over chunks.
__global__ void __launch_bounds__(256)
reduce_kernel() {
    const int d = blockIdx.x * blockDim.x + threadIdx.x;
    float s = 0.f;
    #pragma unroll 8
    for (int c = 0; c < NCHUNK; ++c)
        s += g_partials[c * DMODEL + d];
    g_signal[d] = s;
}

// Kernel 3: out[i] = b[i] + sum_d W[i][d] * signal[d]  (one warp per row)
__global__ void __launch_bounds__(256)
matvec_kernel(const float* __restrict__ W, const float* __restrict__ b,
              float* __restrict__ out) {
    const int warp = (blockIdx.x * blockDim.x + threadIdx.x) >> 5;
    const int lane = threadIdx.x & 31;
    const float* wr = W + warp * DMODEL;

    float s = 0.f;
    #pragma unroll
    for (int k = 0; k < DMODEL / 32; ++k) {
        const int d = k * 32 + lane;
        s = fmaf(wr[d], g_signal[d], s);
    }
    #pragma unroll
    for (int o = 16; o > 0; o >>= 1)
        s += __shfl_down_sync(0xffffffffu, s, o);
    if (lane == 0)
        out[warp] = s + b[warp];
}

extern "C" void kernel_launch(void* const* d_in, const int* in_sizes, int n_in,
                              void* d_out, int out_size) {
    const float* x = (const float*)d_in[0];   // inputs [32768]
    const float* W = (const float*)d_in[1];   // W [1024,1024] row-major
    const float* b = (const float*)d_in[2];   // b [1024]
    float* out = (float*)d_out;               // [1024] float32

    sin_partial_kernel<<<NCHUNK, THREADS1>>>(x);
    reduce_kernel<<<DMODEL / 256, 256>>>();
    matvec_kernel<<<DMODEL / 8, 256>>>(W, b, out);  // 128 blocks * 8 warps = 1024 rows
}

// round 7
// speedup vs baseline: 1.9730x; 1.9730x over previous
#include <cuda_runtime.h>
#include <math.h>

#define L_TOTAL 32768
#define DMODEL  1024
#define NCHUNK  1024
#define L_PER   (L_TOTAL / NCHUNK)     // 32
#define GROUPS  16
#define CH_PER_G (NCHUNK / GROUPS)     // 64
#define THREADS1 256

// Scratch (allocation-free rule: __device__ globals)
__device__ float g_partials[NCHUNK * DMODEL];    // 4 MB
__device__ float g_partials2[GROUPS * DMODEL];   // 64 KB

// Kernel 1: partial sums of sin over a 32-position chunk of L, all 1024 d.
__global__ void __launch_bounds__(THREADS1)
sin_partial_kernel(const float* __restrict__ x) {
    __shared__ float sa[L_PER];
    __shared__ float sc[L_PER];
    const int chunk = blockIdx.x;
    const int l0 = chunk * L_PER;
    const int tid = threadIdx.x;

    if (tid < L_PER) {
        float xv = x[l0 + tid];
        float a  = 6.28318530717958647692f * xv;          // 2*pi*x[l]
        float p  = logf(1.0f + (float)(l0 + tid));        // log1p(l), arg exact in fp32
        sa[tid] = a;
        sc[tid] = a * p;                                  // phase offset
    }
    __syncthreads();

    const float inv = 1.0f / (float)(DMODEL - 1);
    const float t0 = (float)(tid        ) * inv;
    const float t1 = (float)(tid +  256 ) * inv;
    const float t2 = (float)(tid +  512 ) * inv;
    const float t3 = (float)(tid +  768 ) * inv;

    float acc0 = 0.f, acc1 = 0.f, acc2 = 0.f, acc3 = 0.f;

    #pragma unroll 8
    for (int l = 0; l < L_PER; ++l) {
        const float a = sa[l];
        const float c = sc[l];
        acc0 += __sinf(fmaf(a, t0, c));
        acc1 += __sinf(fmaf(a, t1, c));
        acc2 += __sinf(fmaf(a, t2, c));
        acc3 += __sinf(fmaf(a, t3, c));
    }

    float* out = g_partials + chunk * DMODEL;
    out[tid        ] = acc0;
    out[tid +  256 ] = acc1;
    out[tid +  512 ] = acc2;
    out[tid +  768 ] = acc3;
}

// Kernel 2 (stage 1): sum 64 chunks per group -> g_partials2[group][d].
// grid = (DMODEL/256, GROUPS) = (4, 16) = 64 blocks. Coalesced per warp,
// deterministic fixed-order accumulation.
__global__ void __launch_bounds__(256)
reduce1_kernel() {
    const int d = blockIdx.x * 256 + threadIdx.x;
    const int g = blockIdx.y;
    const float* src = g_partials + (g * CH_PER_G) * DMODEL + d;
    float s = 0.f;
    #pragma unroll 16
    for (int c = 0; c < CH_PER_G; ++c)
        s += src[c * DMODEL];
    g_partials2[g * DMODEL + d] = s;
}

// Kernel 3: fused stage-2 reduction + matvec.
// Each block builds signal[1024] in shared (fixed-order sum of 16 group
// partials -> identical & deterministic in every block), then 8 warps each
// compute one output row with float4 loads.
__global__ void __launch_bounds__(256)
matvec_kernel(const float* __restrict__ W, const float* __restrict__ b,
              float* __restrict__ out) {
    __shared__ float ssig[DMODEL];
    const int tid = threadIdx.x;

    {
        float s0 = 0.f, s1 = 0.f, s2 = 0.f, s3 = 0.f;
        #pragma unroll 4
        for (int g = 0; g < GROUPS; ++g) {
            const float* p = g_partials2 + g * DMODEL + tid;
            s0 += p[0];
            s1 += p[256];
            s2 += p[512];
            s3 += p[768];
        }
        ssig[tid      ] = s0;
        ssig[tid + 256] = s1;
        ssig[tid + 512] = s2;
        ssig[tid + 768] = s3;
    }
    __syncthreads();

    const int warp = tid >> 5;
    const int lane = tid & 31;
    const int row  = blockIdx.x * 8 + warp;

    const float4* wr = (const float4*)(W + row * DMODEL);
    const float4* sg = (const float4*)ssig;

    float s = 0.f;
    #pragma unroll
    for (int k = 0; k < DMODEL / 128; ++k) {   // 8 iterations of float4
        float4 w4 = wr[k * 32 + lane];
        float4 s4 = sg[k * 32 + lane];
        s = fmaf(w4.x, s4.x, s);
        s = fmaf(w4.y, s4.y, s);
        s = fmaf(w4.z, s4.z, s);
        s = fmaf(w4.w, s4.w, s);
    }
    #pragma unroll
    for (int o = 16; o > 0; o >>= 1)
        s += __shfl_down_sync(0xffffffffu, s, o);
    if (lane == 0)
        out[row] = s + b[row];
}

extern "C" void kernel_launch(void* const* d_in, const int* in_sizes, int n_in,
                              void* d_out, int out_size) {
    const float* x = (const float*)d_in[0];   // inputs [32768]
    const float* W = (const float*)d_in[1];   // W [1024,1024] row-major
    const float* b = (const float*)d_in[2];   // b [1024]
    float* out = (float*)d_out;               // [1024] float32

    sin_partial_kernel<<<NCHUNK, THREADS1>>>(x);

    dim3 rgrid(DMODEL / 256, GROUPS);
    reduce1_kernel<<<rgrid, 256>>>();

    matvec_kernel<<<DMODEL / 8, 256>>>(W, b, out);
}

// round 12
// speedup vs baseline: 2.1832x; 1.1065x over previous
#include <cuda_runtime.h>
#include <math.h>

#define L_TOTAL 32768
#define DMODEL  1024
#define NCHUNK  1024
#define L_PER   (L_TOTAL / NCHUNK)     // 32
#define GROUPS  32
#define CH_PER_G (NCHUNK / GROUPS)     // 32
#define THREADS1 256

// Scratch (allocation-free rule: __device__ globals)
__device__ float g_partials[NCHUNK * DMODEL];    // 4 MB
__device__ float g_partials2[GROUPS * DMODEL];   // 128 KB
__device__ float g_signal[DMODEL];               // 4 KB

// Kernel 1: partial sin-sums over a 32-position chunk of L, all 1024 d.
// Per (thread, l): one __sincosf seeds sin/cos at phase(d); the 3 sibling
// d's (d+256, d+512, d+768) are obtained by FMA rotations with per-l
// precomputed cos/sin of the phase offsets -> MUFU and FMA pipes balanced.
__global__ void __launch_bounds__(THREADS1)
sin_partial_kernel(const float* __restrict__ x) {
    // per l: [a, c, cos1, sin1] and [cos2, sin2, cos3, sin3]
    __shared__ float4 sd[L_PER][2];
    const int chunk = blockIdx.x;
    const int l0 = chunk * L_PER;
    const int tid = threadIdx.x;

    if (tid < L_PER) {
        const float xv = x[l0 + tid];
        const float a  = 6.28318530717958647692f * xv;      // 2*pi*x[l]
        const float p  = logf(1.0f + (float)(l0 + tid));    // log1p(l)
        const float c  = a * p;
        const float dt = 256.0f / 1023.0f;                  // d-offset step in t
        float s1, c1, s2, c2, s3, c3;
        __sincosf(a * dt,        &s1, &c1);
        __sincosf(a * (2.f*dt),  &s2, &c2);
        __sincosf(a * (3.f*dt),  &s3, &c3);
        sd[tid][0] = make_float4(a, c, c1, s1);
        sd[tid][1] = make_float4(c2, s2, c3, s3);
    }
    __syncthreads();

    const float t0 = (float)tid * (1.0f / 1023.0f);

    float acc0 = 0.f, acc1 = 0.f, acc2 = 0.f, acc3 = 0.f;

    #pragma unroll
    for (int l = 0; l < L_PER; ++l) {
        const float4 A = sd[l][0];       // a, c, cos1, sin1  (warp-uniform: broadcast)
        const float4 B = sd[l][1];       // cos2, sin2, cos3, sin3
        const float ph = fmaf(A.x, t0, A.y);
        float s, cph;
        __sincosf(ph, &s, &cph);         // 2 MUFU
        acc0 += s;
        acc1 = fmaf(s, A.z, acc1);  acc1 = fmaf(cph, A.w, acc1);
        acc2 = fmaf(s, B.x, acc2);  acc2 = fmaf(cph, B.y, acc2);
        acc3 = fmaf(s, B.z, acc3);  acc3 = fmaf(cph, B.w, acc3);
    }

    float* out = g_partials + chunk * DMODEL;
    out[tid      ] = acc0;
    out[tid + 256] = acc1;
    out[tid + 512] = acc2;
    out[tid + 768] = acc3;
}

// Kernel 2 (stage 1): sum 32 chunks per group. grid=(4,32)=128 blocks.
// Coalesced, deterministic fixed order.
__global__ void __launch_bounds__(256)
reduce1_kernel() {
    const int d = blockIdx.x * 256 + threadIdx.x;
    const int g = blockIdx.y;
    const float* src = g_partials + (g * CH_PER_G) * DMODEL + d;
    float s = 0.f;
    #pragma unroll
    for (int c = 0; c < CH_PER_G; ++c)
        s += src[c * DMODEL];
    g_partials2[g * DMODEL + d] = s;
}

// Kernel 3 (stage 2): 1 block x 1024 threads -> g_signal[1024].
__global__ void __launch_bounds__(1024)
reduce2_kernel() {
    const int d = threadIdx.x;
    float s = 0.f;
    #pragma unroll
    for (int g = 0; g < GROUPS; ++g)
        s += g_partials2[g * DMODEL + d];
    g_signal[d] = s;
}

// Kernel 4: matvec. Each block caches signal in shared (4KB), 8 warps each
// compute one output row with float4 loads + shuffle reduction.
__global__ void __launch_bounds__(256)
matvec_kernel(const float* __restrict__ W, const float* __restrict__ b,
              float* __restrict__ out) {
    __shared__ float ssig[DMODEL];
    const int tid = threadIdx.x;

    ((float4*)ssig)[tid] = ((const float4*)g_signal)[tid];
    __syncthreads();

    const int warp = tid >> 5;
    const int lane = tid & 31;
    const int row  = blockIdx.x * 8 + warp;

    const float4* wr = (const float4*)(W + row * DMODEL);
    const float4* sg = (const float4*)ssig;

    float s = 0.f;
    #pragma unroll
    for (int k = 0; k < DMODEL / 128; ++k) {   // 8 iterations of float4
        float4 w4 = wr[k * 32 + lane];
        float4 s4 = sg[k * 32 + lane];
        s = fmaf(w4.x, s4.x, s);
        s = fmaf(w4.y, s4.y, s);
        s = fmaf(w4.z, s4.z, s);
        s = fmaf(w4.w, s4.w, s);
    }
    #pragma unroll
    for (int o = 16; o > 0; o >>= 1)
        s += __shfl_down_sync(0xffffffffu, s, o);
    if (lane == 0)
        out[row] = s + b[row];
}

extern "C" void kernel_launch(void* const* d_in, const int* in_sizes, int n_in,
                              void* d_out, int out_size) {
    const float* x = (const float*)d_in[0];   // inputs [32768]
    const float* W = (const float*)d_in[1];   // W [1024,1024] row-major
    const float* b = (const float*)d_in[2];   // b [1024]
    float* out = (float*)d_out;               // [1024] float32

    sin_partial_kernel<<<NCHUNK, THREADS1>>>(x);

    dim3 rgrid(DMODEL / 256, GROUPS);
    reduce1_kernel<<<rgrid, 256>>>();
    reduce2_kernel<<<1, 1024>>>();

    matvec_kernel<<<DMODEL / 8, 256>>>(W, b, out);
}